// round 13
// baseline (speedup 1.0000x reference)
#include <cuda_runtime.h>
#include <cuda_bf16.h>
#include <math.h>

// FFMCell: new_state = state * gamma(t) + x, gamma = exp((-|a| + i b) * t)
// T=4096, TRACE=64, CTX=64.
//
// R13: persistent kernel (grid = 888 = 148 SMs x 6 blocks), each block
// processes ~4-5 t-tiles. Factor computation is software-pipelined across
// tiles with double-buffered smem: while tile i streams (JIT float4 body,
// R10's proven loop), threads 0-127 compute tile i+1's factors into the
// other buffer. The per-tile barrier therefore has no transcendental chain
// behind it. One barrier per tile, factors amortized 64 sincos / 4096 elts.

__global__ void __launch_bounds__(256, 6) ffm_r13_kernel(
    const float4* __restrict__ sre,
    const float4* __restrict__ sim,
    const float4* __restrict__ xre,
    const float4* __restrict__ xim,
    const float* __restrict__ a,
    const float* __restrict__ b,
    const int* __restrict__ ivec,
    const int* __restrict__ jvec,
    float* __restrict__ out,
    float* __restrict__ out_tail,
    int T)
{
    const int tid = threadIdx.x;

    __shared__ float  s_dec[2][64];
    __shared__ float2 s_cs [2][64];

    // Factor computation for tile tt into buffer p (threads 0..128 only).
    auto factors = [&](int tt, int p) {
        if (tt >= T) return;
        if (tid < 64) {
            const float tf = (float)__ldg(&jvec[tt]);
            float sn, cs;
            sincosf(__ldg(&b[tid]) * tf, &sn, &cs);   // same fp32 ops as ref
            s_cs[p][tid] = make_float2(cs, sn);
        } else if (tid < 128) {
            const float tf = (float)__ldg(&jvec[tt]);
            s_dec[p][tid - 64] = expf(-fabsf(__ldg(&a[tid - 64])) * tf);
        } else if (tid == 128 && out_tail != nullptr) {
            out_tail[tt] = (float)(__ldg(&jvec[tt]) + __ldg(&ivec[tt]));
        }
    };

    int tile = blockIdx.x;
    if (tile >= T) return;

    // Prime the pipeline: tile-0 factors into buffer 0.
    factors(tile, 0);
    __syncthreads();

    float4* __restrict__ out4 = reinterpret_cast<float4*>(out);
    const int cbase = (tid & 15) << 1;       // float4 index into s_cs
    const int tr0   = tid >> 4;              // base trace row

    int p = 0;
    for (; tile < T; tile += gridDim.x) {
        // Pipeline: next tile's factors into the other buffer. Warps 4-7
        // have no work here and start streaming immediately; warps 0-3's
        // MUFU latency overlaps the streaming below.
        factors(tile + gridDim.x, p ^ 1);

        const int g0 = tile * 1024 + tid;
        const float4* s_cs4 = reinterpret_cast<const float4*>(s_cs[p]);
        const float4 csA = s_cs4[cbase];
        const float4 csB = s_cs4[cbase + 1];

        #pragma unroll
        for (int it = 0; it < 4; ++it) {
            const int g = g0 + it * 256;

            const float4 sr = __ldcs(&sre[g]);
            const float4 si = __ldcs(&sim[g]);
            const float4 xr = __ldcs(&xre[g]);
            const float4 xi = __ldcs(&xim[g]);

            const float dec = s_dec[p][it * 16 + tr0];

            const float gr0 = dec * csA.x, gi0 = dec * csA.y;
            const float gr1 = dec * csA.z, gi1 = dec * csA.w;
            const float gr2 = dec * csB.x, gi2 = dec * csB.y;
            const float gr3 = dec * csB.z, gi3 = dec * csB.w;

            float4 o0, o1;
            o0.x = fmaf(sr.x, gr0, fmaf(-si.x, gi0, xr.x));
            o0.y = fmaf(sr.x, gi0, fmaf( si.x, gr0, xi.x));
            o0.z = fmaf(sr.y, gr1, fmaf(-si.y, gi1, xr.y));
            o0.w = fmaf(sr.y, gi1, fmaf( si.y, gr1, xi.y));
            o1.x = fmaf(sr.z, gr2, fmaf(-si.z, gi2, xr.z));
            o1.y = fmaf(sr.z, gi2, fmaf( si.z, gr2, xi.z));
            o1.z = fmaf(sr.w, gr3, fmaf(-si.w, gi3, xr.w));
            o1.w = fmaf(sr.w, gi3, fmaf( si.w, gr3, xi.w));

            out4[2 * g]     = o0;
            out4[2 * g + 1] = o1;
        }

        // Single barrier per tile: protects buf[p^1] writes (this iter) vs
        // reads (next iter), and buf[p] reads (this iter) vs overwrite
        // (next iter). Nothing is chained behind it.
        __syncthreads();
        p ^= 1;
    }
}

extern "C" void kernel_launch(void* const* d_in, const int* in_sizes, int n_in,
                              void* d_out, int out_size)
{
    const float4* sre = (const float4*)d_in[0];
    const float4* sim = (const float4*)d_in[1];
    const float4* xre = (const float4*)d_in[2];
    const float4* xim = (const float4*)d_in[3];
    const float*  a   = (const float*)d_in[4];
    const float*  b   = (const float*)d_in[5];
    const int*    iv  = (const int*)d_in[6];
    const int*    jv  = (const int*)d_in[7];

    const int T = in_sizes[6];                      // 4096
    const long long N = (long long)in_sizes[0];     // T*TRACE*CTX

    float* out = (float*)d_out;
    float* out_tail = nullptr;
    if ((long long)out_size > 2LL * N) {
        out_tail = out + 2LL * N;
    }

    // Persistent grid: 6 blocks/SM x 148 SMs (clamped to T).
    int grid = 148 * 6;
    if (grid > T) grid = T;

    ffm_r13_kernel<<<grid, 256>>>(sre, sim, xre, xim, a, b, iv, jv,
                                  out, out_tail, T);
}